// round 4
// baseline (speedup 1.0000x reference)
#include <cuda_runtime.h>
#include <cuda_bf16.h>
#include <cstdint>

#define GRID_DIM   201
#define GRID_ELEMS (GRID_DIM * GRID_DIM)        // 40401
#define TILE_FLOATS 4096                        // 16KB per array per tile
#define TILE_BYTES  (TILE_FLOATS * 4)

// smem layout (dynamic):
#define SMEM_WG     0
#define SMEM_MBAR   161616                      // 2 mbarriers (16B)
#define SMEM_RED    161664                      // 32 floats (128B)
#define SMEM_BUF    161792                      // 128-aligned
// buffers: stage0: pred[16K] lab[16K]; stage1: pred[16K] lab[16K]
#define SMEM_TOTAL  (SMEM_BUF + 4 * TILE_BYTES) // 227,328

__device__ float        g_partial = 0.0f;
__device__ unsigned int g_count   = 0;

__device__ __forceinline__ uint32_t smem_u32(const void* p) {
    uint32_t a;
    asm("{ .reg .u64 t; cvta.to.shared.u64 t, %1; cvt.u32.u64 %0, t; }"
        : "=r"(a) : "l"(p));
    return a;
}

__device__ __forceinline__ void mbar_init(uint32_t mbar, uint32_t cnt) {
    asm volatile("mbarrier.init.shared.b64 [%0], %1;" :: "r"(mbar), "r"(cnt) : "memory");
}
__device__ __forceinline__ void mbar_expect_tx(uint32_t mbar, uint32_t bytes) {
    asm volatile("mbarrier.arrive.expect_tx.shared.b64 _, [%0], %1;"
                 :: "r"(mbar), "r"(bytes) : "memory");
}
__device__ __forceinline__ void bulk_g2s(uint32_t dst, const void* src,
                                         uint32_t bytes, uint32_t mbar) {
    asm volatile(
        "cp.async.bulk.shared::cluster.global.mbarrier::complete_tx::bytes "
        "[%0], [%1], %2, [%3];"
        :: "r"(dst), "l"(src), "r"(bytes), "r"(mbar) : "memory");
}
__device__ __forceinline__ void mbar_wait(uint32_t mbar, uint32_t parity) {
    uint32_t done;
    do {
        asm volatile(
            "{\n\t.reg .pred p;\n\t"
            "mbarrier.try_wait.parity.acquire.cta.shared::cta.b64 p, [%1], %2, 0x989680;\n\t"
            "selp.b32 %0, 1, 0, p;\n\t}"
            : "=r"(done) : "r"(mbar), "r"(parity) : "memory");
    } while (!done);
}

extern __shared__ char smem_raw[];

__device__ __forceinline__ float sample_w_smem(const float* s_wg,
                                               float px, float py) {
    // floor((p*180-90)/0.9)+100 == floor(p*200); same for lon with /1.8.
    int xi = __float2int_rd(px * 200.0f);
    int yi = __float2int_rd(py * 200.0f);
    xi = min(max(xi, 0), GRID_DIM - 1);
    yi = min(max(yi, 0), GRID_DIM - 1);
    return s_wg[xi * GRID_DIM + yi];
}

__device__ __forceinline__ float proc4(float4 p, float4 l, const float* s_wg) {
    float e0 = fabsf(p.x - l.x) + fabsf(p.y - l.y);
    float e1 = fabsf(p.z - l.z) + fabsf(p.w - l.w);
    float w0 = sample_w_smem(s_wg, p.x, p.y);
    float w1 = sample_w_smem(s_wg, p.z, p.w);
    return fmaf(e0, fmaf(-0.1f, w0, 1.1f), e1 * fmaf(-0.1f, w1, 1.1f));
}

__global__ void __launch_bounds__(1024, 1)
wmse_kernel(const float* __restrict__ pred,
            const float* __restrict__ lab,
            const float* __restrict__ wg,
            float* __restrict__ out,
            int total,            // total floats per array (B*2)
            float inv_count)
{
    float* s_wg = reinterpret_cast<float*>(smem_raw + SMEM_WG);
    float* s_red = reinterpret_cast<float*>(smem_raw + SMEM_RED);
    const uint32_t smem_base = smem_u32(smem_raw);
    const uint32_t mbar0 = smem_base + SMEM_MBAR;
    const uint32_t buf_base = smem_base + SMEM_BUF;

    const int tid = threadIdx.x;
    const int bid = blockIdx.x;
    const int G   = gridDim.x;

    // ---- fill weight grid into smem ----
    {
        const float4* __restrict__ wg4 = reinterpret_cast<const float4*>(wg);
        float4* s4 = reinterpret_cast<float4*>(s_wg);
        for (int j = tid; j < GRID_ELEMS / 4; j += blockDim.x)
            s4[j] = __ldg(&wg4[j]);
        if (tid == 0)
            s_wg[GRID_ELEMS - 1] = __ldg(&wg[GRID_ELEMS - 1]);
    }

    // ---- init mbarriers ----
    if (tid == 0) {
        mbar_init(mbar0, 1);
        mbar_init(mbar0 + 8, 1);
        asm volatile("fence.proxy.async.shared::cta;" ::: "memory");
    }
    __syncthreads();

    const int NT = total / TILE_FLOATS;   // full tiles (4096 here)

    // my tiles: bid, bid+G, bid+2G, ...
    // prologue: issue first two tiles
    if (tid == 0) {
        #pragma unroll
        for (int n = 0; n < 2; n++) {
            int t = bid + n * G;
            if (t < NT) {
                uint32_t mb = mbar0 + 8u * n;
                uint32_t bp = buf_base + (uint32_t)n * 2u * TILE_BYTES;
                mbar_expect_tx(mb, 2 * TILE_BYTES);
                bulk_g2s(bp,              pred + (size_t)t * TILE_FLOATS, TILE_BYTES, mb);
                bulk_g2s(bp + TILE_BYTES, lab  + (size_t)t * TILE_FLOATS, TILE_BYTES, mb);
            }
        }
    }

    float acc = 0.0f;

    for (int n = 0, t = bid; t < NT; n++, t += G) {
        int s = n & 1;
        uint32_t parity = (n >> 1) & 1;
        uint32_t mb = mbar0 + 8u * s;
        mbar_wait(mb, parity);

        const float4* sp = reinterpret_cast<const float4*>(
            smem_raw + SMEM_BUF + (size_t)s * 2 * TILE_BYTES);
        const float4* sl = reinterpret_cast<const float4*>(
            smem_raw + SMEM_BUF + (size_t)s * 2 * TILE_BYTES + TILE_BYTES);

        // 1024 float4 per buffer, 1024 threads: 1 chunk each
        float4 p = sp[tid];
        float4 l = sl[tid];
        acc += proc4(p, l, s_wg);

        __syncthreads();   // everyone done reading stage s

        // refill stage s with tile n+2
        if (tid == 0) {
            int t2 = bid + (n + 2) * G;
            if (t2 < NT) {
                uint32_t bp = buf_base + (uint32_t)s * 2u * TILE_BYTES;
                mbar_expect_tx(mb, 2 * TILE_BYTES);
                bulk_g2s(bp,              pred + (size_t)t2 * TILE_FLOATS, TILE_BYTES, mb);
                bulk_g2s(bp + TILE_BYTES, lab  + (size_t)t2 * TILE_FLOATS, TILE_BYTES, mb);
            }
        }
    }

    // ---- generic tail (zero iterations for B*2 = 2^24) ----
    {
        int rem_start = NT * TILE_FLOATS;
        int rem_vec = (total - rem_start) / 4;
        if (rem_vec > 0 && bid == 0) {
            const float4* p4 = reinterpret_cast<const float4*>(pred + rem_start);
            const float4* l4 = reinterpret_cast<const float4*>(lab + rem_start);
            for (int i = tid; i < rem_vec; i += blockDim.x)
                acc += proc4(__ldg(p4 + i), __ldg(l4 + i), s_wg);
        }
    }

    // ---- reduction ----
    #pragma unroll
    for (int off = 16; off > 0; off >>= 1)
        acc += __shfl_xor_sync(0xFFFFFFFFu, acc, off);

    int lane = tid & 31;
    int wid  = tid >> 5;
    if (lane == 0) s_red[wid] = acc;
    __syncthreads();

    if (wid == 0) {
        float v = (lane < (int)(blockDim.x >> 5)) ? s_red[lane] : 0.0f;
        #pragma unroll
        for (int off = 16; off > 0; off >>= 1)
            v += __shfl_xor_sync(0xFFFFFFFFu, v, off);

        if (lane == 0) {
            atomicAdd(&g_partial, v);
            __threadfence();
            unsigned int prev = atomicAdd(&g_count, 1u);
            if (prev == gridDim.x - 1) {
                float totalv = *((volatile float*)&g_partial);
                out[0] = totalv * inv_count;
                g_partial = 0.0f;
                g_count   = 0u;
            }
        }
    }
}

extern "C" void kernel_launch(void* const* d_in, const int* in_sizes, int n_in,
                              void* d_out, int out_size) {
    const float* pred = (const float*)d_in[0];
    const float* lab  = (const float*)d_in[1];
    const float* wg   = (const float*)d_in[2];
    float* out = (float*)d_out;

    int total = in_sizes[0];              // B*2 floats per array
    float inv_count = 1.0f / (float)total;

    static bool attr_done = false;
    if (!attr_done) {
        cudaFuncSetAttribute(wmse_kernel,
                             cudaFuncAttributeMaxDynamicSharedMemorySize,
                             SMEM_TOTAL);
        attr_done = true;
    }

    int sm_count = 148;
    cudaDeviceGetAttribute(&sm_count, cudaDevAttrMultiProcessorCount, 0);

    wmse_kernel<<<sm_count, 1024, SMEM_TOTAL>>>(pred, lab, wg, out,
                                                total, inv_count);
}

// round 5
// speedup vs baseline: 1.0427x; 1.0427x over previous
#include <cuda_runtime.h>
#include <cuda_bf16.h>
#include <cstdint>

#define GRID_DIM 201

// Self-resetting accumulator state (zero at load; finishing block resets each
// launch so graph replays stay deterministic).
__device__ float        g_partial = 0.0f;
__device__ unsigned int g_count   = 0;

__device__ __forceinline__ float sample_w(const float* __restrict__ wg,
                                          float px, float py) {
    // floor((p*180-90)/0.9)+100 == floor(p*200); same for lon with /1.8.
    int xi = __float2int_rd(px * 200.0f);
    int yi = __float2int_rd(py * 200.0f);
    xi = min(max(xi, 0), GRID_DIM - 1);
    yi = min(max(yi, 0), GRID_DIM - 1);
    return __ldg(&wg[xi * GRID_DIM + yi]);
}

__device__ __forceinline__ float proc4(float4 p, float4 l,
                                       const float* __restrict__ wg) {
    float e0 = fabsf(p.x - l.x) + fabsf(p.y - l.y);   // sample 0
    float e1 = fabsf(p.z - l.z) + fabsf(p.w - l.w);   // sample 1
    float w0 = sample_w(wg, p.x, p.y);
    float w1 = sample_w(wg, p.z, p.w);
    // err * (1 + alpha - alpha*w)
    return fmaf(e0, fmaf(-0.1f, w0, 1.1f), e1 * fmaf(-0.1f, w1, 1.1f));
}

__global__ void __launch_bounds__(1024, 2)
wmse_kernel(const float* __restrict__ pred,
            const float* __restrict__ lab,
            const float* __restrict__ wg,
            float* __restrict__ out,
            int nvec,            // float4 chunks (2 samples each)
            float inv_count)     // 1/(B*2)
{
    const float4* __restrict__ p4 = reinterpret_cast<const float4*>(pred);
    const float4* __restrict__ l4 = reinterpret_cast<const float4*>(lab);

    float acc = 0.0f;
    const int stride = gridDim.x * blockDim.x;
    int i = blockIdx.x * blockDim.x + threadIdx.x;

    // Unroll-by-2 grid-stride: 4 independent 16B loads in flight before the
    // dependent gathers.
    for (; i + stride < nvec; i += 2 * stride) {
        float4 p0 = p4[i];
        float4 l0 = l4[i];
        float4 p1 = p4[i + stride];
        float4 l1 = l4[i + stride];
        acc += proc4(p0, l0, wg);
        acc += proc4(p1, l1, wg);
    }
    if (i < nvec)
        acc += proc4(p4[i], l4[i], wg);

    // ---- block reduction ----
    #pragma unroll
    for (int off = 16; off > 0; off >>= 1)
        acc += __shfl_xor_sync(0xFFFFFFFFu, acc, off);

    __shared__ float warp_part[32];
    int lane = threadIdx.x & 31;
    int wid  = threadIdx.x >> 5;
    if (lane == 0) warp_part[wid] = acc;
    __syncthreads();

    if (wid == 0) {
        float v = (lane < (int)(blockDim.x >> 5)) ? warp_part[lane] : 0.0f;
        #pragma unroll
        for (int off = 16; off > 0; off >>= 1)
            v += __shfl_xor_sync(0xFFFFFFFFu, v, off);

        if (lane == 0) {
            atomicAdd(&g_partial, v);
            __threadfence();
            unsigned int prev = atomicAdd(&g_count, 1u);
            if (prev == gridDim.x - 1) {
                // All other partials are visible (their fences precede
                // their counter increments).
                float total = *((volatile float*)&g_partial);
                out[0] = total * inv_count;
                g_partial = 0.0f;   // reset for next graph replay
                g_count   = 0u;
            }
        }
    }
}

extern "C" void kernel_launch(void* const* d_in, const int* in_sizes, int n_in,
                              void* d_out, int out_size) {
    const float* pred = (const float*)d_in[0];
    const float* lab  = (const float*)d_in[1];
    const float* wg   = (const float*)d_in[2];
    float* out = (float*)d_out;

    int total = in_sizes[0];          // B*2 floats per array
    int nvec  = total / 4;
    float inv_count = 1.0f / (float)total;

    int sm_count = 148;
    cudaDeviceGetAttribute(&sm_count, cudaDevAttrMultiProcessorCount, 0);

    // Small launch (graph-replay overhead scales with CTA count): 2 CTAs/SM
    // of 1024 threads = full 64-warp occupancy, only ~304 CTAs.
    wmse_kernel<<<sm_count * 2, 1024>>>(pred, lab, wg, out, nvec, inv_count);
}